// round 8
// baseline (speedup 1.0000x reference)
#include <cuda_runtime.h>
#include <cuda_bf16.h>
#include <math_constants.h>

// Problem: B=512, N=2048, D=128
//   Qp    = Q @ W1.T + b1                       (B,D)
//   alpha = einsum('bnd,bd->bn', K@W2.T+b2, Qp) (B,N)
//   alpha -= (1-adj)*1e30 ; w = softmax(alpha)  (B,N)
//   attn_sum = einsum('bn,bnd->bd', w, V)       (B,D)
// Outputs concatenated: attn_weight (B*1*N floats) then attn_sum (B*D floats).
//
// Algebraic collapse: alpha[b,n] = K[b,n] . (Qp[b] @ W2) + const(b);
// the per-row constant cancels in softmax, so the big K@W2.T GEMM is gone.

#define B_ 512
#define N_ 2048
#define D_ 128

// scratch for q-tilde (allocation-free rule: __device__ global)
__device__ float g_qt[B_ * D_];

// ---------------------------------------------------------------------------
// Kernel 1: q_tilde[b] = (Q[b] @ W1.T + b1) @ W2        grid=B, block=D
// ---------------------------------------------------------------------------
__global__ void __launch_bounds__(D_) qt_kernel(
    const float* __restrict__ Q, const float* __restrict__ W1,
    const float* __restrict__ b1, const float* __restrict__ W2,
    float* __restrict__ qt)
{
    __shared__ float sQ[D_];
    __shared__ float sQp[D_];
    const int b = blockIdx.x;
    const int t = threadIdx.x;

    sQ[t] = Q[b * D_ + t];
    __syncthreads();

    // Qp[t] = b1[t] + sum_d Q[b,d] * W1[t,d]   (W1 row t is contiguous)
    float acc = b1[t];
    const float4* w1row = (const float4*)(W1 + t * D_);
#pragma unroll 8
    for (int d = 0; d < D_ / 4; d++) {
        float4 w = w1row[d];
        acc += sQ[4*d+0]*w.x + sQ[4*d+1]*w.y + sQ[4*d+2]*w.z + sQ[4*d+3]*w.w;
    }
    sQp[t] = acc;
    __syncthreads();

    // qt[t] = sum_e Qp[e] * W2[e,t]   (coalesced across threads per e)
    float acc2 = 0.f;
#pragma unroll 8
    for (int e = 0; e < D_; e++)
        acc2 += sQp[e] * W2[e * D_ + t];
    qt[b * D_ + t] = acc2;
}

// ---------------------------------------------------------------------------
// Kernel 2: per-b fused  alpha -> mask -> softmax -> weights out -> w@V
// grid=B, block=1024 (32 warps)
// ---------------------------------------------------------------------------
__global__ void __launch_bounds__(1024, 2) attn_kernel(
    const float* __restrict__ K, const float* __restrict__ V,
    const float* __restrict__ adj, const float* __restrict__ qt,
    float* __restrict__ attn_w, float* __restrict__ attn_sum)
{
    __shared__ float s_alpha[N_];        // 8 KB
    __shared__ float s_red[32];
    __shared__ float s_part[8][D_];      // 4 KB

    const int b    = blockIdx.x;
    const int tid  = threadIdx.x;
    const int lane = tid & 31;
    const int warp = tid >> 5;           // 0..31

    const float* __restrict__ Kb   = K   + (size_t)b * N_ * D_;
    const float* __restrict__ Vb   = V   + (size_t)b * N_ * D_;
    const float* __restrict__ adjb = adj + (size_t)b * N_;

    // q-tilde: 4 elements per lane, held in registers
    const float4 q = *(const float4*)(qt + b * D_ + lane * 4);

    // ---- pass 1: alpha[n] = K[b,n].qtilde - (1-adj)*1e30 ----
    for (int n = warp; n < N_; n += 32) {
        float4 k = *(const float4*)(Kb + (size_t)n * D_ + lane * 4);
        float p = k.x*q.x + k.y*q.y + k.z*q.z + k.w*q.w;
        p += __shfl_xor_sync(0xffffffffu, p, 16);
        p += __shfl_xor_sync(0xffffffffu, p, 8);
        p += __shfl_xor_sync(0xffffffffu, p, 4);
        p += __shfl_xor_sync(0xffffffffu, p, 2);
        p += __shfl_xor_sync(0xffffffffu, p, 1);
        if (lane == 0)
            s_alpha[n] = p - (1.0f - adjb[n]) * 1e30f;
    }
    __syncthreads();

    // ---- softmax: block max ----
    float m = -CUDART_INF_F;
    for (int n = tid; n < N_; n += 1024) m = fmaxf(m, s_alpha[n]);
#pragma unroll
    for (int o = 16; o; o >>= 1) m = fmaxf(m, __shfl_xor_sync(0xffffffffu, m, o));
    if (lane == 0) s_red[warp] = m;
    __syncthreads();
    if (warp == 0) {
        m = s_red[lane];
#pragma unroll
        for (int o = 16; o; o >>= 1) m = fmaxf(m, __shfl_xor_sync(0xffffffffu, m, o));
        if (lane == 0) s_red[0] = m;
    }
    __syncthreads();
    m = s_red[0];
    __syncthreads();   // before s_red reuse

    // ---- softmax: exp + block sum ----
    float s = 0.f;
    for (int n = tid; n < N_; n += 1024) {
        float e = __expf(s_alpha[n] - m);
        s_alpha[n] = e;
        s += e;
    }
#pragma unroll
    for (int o = 16; o; o >>= 1) s += __shfl_xor_sync(0xffffffffu, s, o);
    if (lane == 0) s_red[warp] = s;
    __syncthreads();
    if (warp == 0) {
        s = s_red[lane];
#pragma unroll
        for (int o = 16; o; o >>= 1) s += __shfl_xor_sync(0xffffffffu, s, o);
        if (lane == 0) s_red[0] = s;
    }
    __syncthreads();
    const float inv = 1.0f / s_red[0];

    // ---- normalize, write attn_weight ----
    float* __restrict__ wout = attn_w + (size_t)b * N_;
    for (int n = tid; n < N_; n += 1024) {
        float w = s_alpha[n] * inv;
        s_alpha[n] = w;
        wout[n] = w;
    }
    __syncthreads();

    // ---- pass 2: attn_sum[d] = sum_n w[n] * V[b,n,d] ----
    const int d = tid & 127;             // 0..127
    const int g = tid >> 7;              // 0..7
    float acc = 0.f;
#pragma unroll 4
    for (int n = g; n < N_; n += 8)
        acc += s_alpha[n] * Vb[(size_t)n * D_ + d];
    s_part[g][d] = acc;
    __syncthreads();
    if (g == 0) {
        float t2 = 0.f;
#pragma unroll
        for (int gg = 0; gg < 8; gg++) t2 += s_part[gg][d];
        attn_sum[(size_t)b * D_ + d] = t2;
    }
}

// ---------------------------------------------------------------------------
extern "C" void kernel_launch(void* const* d_in, const int* in_sizes, int n_in,
                              void* d_out, int out_size)
{
    const float* Q   = (const float*)d_in[0];   // (B,D)
    const float* K   = (const float*)d_in[1];   // (B,N,D)
    const float* V   = (const float*)d_in[2];   // (B,N,D)
    const float* adj = (const float*)d_in[3];   // (B,N)
    // d_in[4] = s_mask (int32, unused)
    const float* W1  = (const float*)d_in[5];   // (D,D)
    const float* b1  = (const float*)d_in[6];   // (D,)
    const float* W2  = (const float*)d_in[7];   // (D,D)
    // d_in[8] = b2 (cancels in softmax)

    float* out_w   = (float*)d_out;                       // (B,1,N)
    float* out_sum = (float*)d_out + (size_t)B_ * N_;     // (B,D)

    float* qt;
    cudaGetSymbolAddress((void**)&qt, g_qt);

    qt_kernel<<<B_, D_>>>(Q, W1, b1, W2, qt);
    attn_kernel<<<B_, 1024>>>(K, V, adj, qt, out_w, out_sum);
}

// round 9
// speedup vs baseline: 1.1314x; 1.1314x over previous
#include <cuda_runtime.h>
#include <cuda_bf16.h>
#include <math_constants.h>

// B=512, N=2048, D=128.
// alpha[b,n] = K[b,n] . qtilde[b]  (qtilde = (Q@W1.T+b1)@W2; b2 term cancels in softmax)
// Single-pass online softmax streams K and V together (flash-style), split-N=2
// for wave balance, then a small merge kernel normalizes weights + attn_sum.

#define B_ 512
#define N_ 2048
#define D_ 128
#define SPLIT 2
#define CHUNK (N_ / SPLIT)          // 1024
#define UNITS (B_ * SPLIT)          // 1024

__device__ float g_qt[B_ * D_];
__device__ float g_pm[UNITS];
__device__ float g_ps[UNITS];
__device__ float g_pacc[UNITS * D_];

// ---------------------------------------------------------------------------
// Kernel 1: q_tilde[b] = (Q[b] @ W1.T + b1) @ W2        grid=B, block=D
// ---------------------------------------------------------------------------
__global__ void __launch_bounds__(D_) qt_kernel(
    const float* __restrict__ Q, const float* __restrict__ W1,
    const float* __restrict__ b1, const float* __restrict__ W2,
    float* __restrict__ qt)
{
    __shared__ float sQ[D_];
    __shared__ float sQp[D_];
    const int b = blockIdx.x;
    const int t = threadIdx.x;

    sQ[t] = Q[b * D_ + t];
    __syncthreads();

    float acc = b1[t];
    const float4* w1row = (const float4*)(W1 + t * D_);
#pragma unroll 8
    for (int d = 0; d < D_ / 4; d++) {
        float4 w = w1row[d];
        acc += sQ[4*d+0]*w.x + sQ[4*d+1]*w.y + sQ[4*d+2]*w.z + sQ[4*d+3]*w.w;
    }
    sQp[t] = acc;
    __syncthreads();

    float acc2 = 0.f;
#pragma unroll 8
    for (int e = 0; e < D_; e++)
        acc2 += sQp[e] * W2[e * D_ + t];
    qt[b * D_ + t] = acc2;
}

// ---------------------------------------------------------------------------
// Kernel 2: per-(b,part) single-pass online softmax over CHUNK rows.
// grid = UNITS (1024), block = 1024 (32 warps), occ 1 (64 regs available).
// Streams K and V interleaved; writes unnormalized alpha into attn_w and a
// per-unit partial (m, s, acc[128]) into global scratch.
// ---------------------------------------------------------------------------
__global__ void __launch_bounds__(1024, 1) attn_main(
    const float* __restrict__ K, const float* __restrict__ V,
    const float* __restrict__ adj, const float* __restrict__ qt,
    float* __restrict__ attn_w)
{
    __shared__ float s_alpha[CHUNK];       // 4 KB
    __shared__ float s_acc[32][D_];        // 16 KB
    __shared__ float s_m[32], s_s[32];
    __shared__ float s_MS[2];

    const int u    = blockIdx.x;
    const int b    = u >> 1;
    const int part = u & 1;
    const int tid  = threadIdx.x;
    const int lane = tid & 31;
    const int warp = tid >> 5;             // 0..31
    const int base = part * CHUNK;

    const float4* __restrict__ K4   = (const float4*)(K + (size_t)b * N_ * D_);
    const float4* __restrict__ V4   = (const float4*)(V + (size_t)b * N_ * D_);
    const float*  __restrict__ adjb = adj + (size_t)b * N_;

    const float4 q = *((const float4*)(qt + b * D_) + lane);

    float  m = -CUDART_INF_F;
    float  s = 0.f;
    float4 acc = make_float4(0.f, 0.f, 0.f, 0.f);

    // warp handles rows n = base + warp + 32*j, j=0..31; unroll 2 rows/iter.
#pragma unroll 4
    for (int jj = 0; jj < 16; jj++) {
        const int    n0 = base + 64 * jj + warp;          // second row: n0+32
        const size_t o0 = (size_t)n0 * 32 + lane;         // float4 offset
        float4 k0 = K4[o0];
        float4 k1 = K4[o0 + 1024];                        // +32 rows
        float4 v0 = V4[o0];
        float4 v1 = V4[o0 + 1024];
        float adj0 = adjb[n0];
        float adj1 = adjb[n0 + 32];

        float p0 = k0.x*q.x + k0.y*q.y + k0.z*q.z + k0.w*q.w;
        float p1 = k1.x*q.x + k1.y*q.y + k1.z*q.z + k1.w*q.w;
#pragma unroll
        for (int o = 16; o; o >>= 1) {
            p0 += __shfl_xor_sync(0xffffffffu, p0, o);
            p1 += __shfl_xor_sync(0xffffffffu, p1, o);
        }
        float a0 = p0 - (1.f - adj0) * 1e30f;
        float a1 = p1 - (1.f - adj1) * 1e30f;
        if (lane == 0) {
            s_alpha[64 * jj + warp]      = a0;
            s_alpha[64 * jj + warp + 32] = a1;
        }

        float nm = fmaxf(m, fmaxf(a0, a1));
        float f  = __expf(m - nm);
        float e0 = __expf(a0 - nm);
        float e1 = __expf(a1 - nm);
        s = s * f + e0 + e1;
        acc.x = acc.x * f + e0 * v0.x + e1 * v1.x;
        acc.y = acc.y * f + e0 * v0.y + e1 * v1.y;
        acc.z = acc.z * f + e0 * v0.z + e1 * v1.z;
        acc.w = acc.w * f + e0 * v0.w + e1 * v1.w;
        m = nm;
    }

    // ---- CTA merge of 32 warp partials ----
    if (lane == 0) { s_m[warp] = m; s_s[warp] = s; }
    *(float4*)&s_acc[warp][lane * 4] = acc;
    __syncthreads();

    if (warp == 0) {
        float mw = s_m[lane];
        float M  = mw;
#pragma unroll
        for (int o = 16; o; o >>= 1) M = fmaxf(M, __shfl_xor_sync(0xffffffffu, M, o));
        float sw = s_s[lane] * __expf(mw - M);
#pragma unroll
        for (int o = 16; o; o >>= 1) sw += __shfl_xor_sync(0xffffffffu, sw, o);
        if (lane == 0) { s_MS[0] = M; s_MS[1] = sw; }
    }
    __syncthreads();
    const float M = s_MS[0];

    // stage 2: 8 groups of 128 threads each fold 4 scaled warp partials
    const int g = tid >> 7;                // 0..7
    const int d = tid & 127;
    float p4 = 0.f;
#pragma unroll
    for (int w = 0; w < 4; w++) {
        const int wi = g * 4 + w;
        p4 += s_acc[wi][d] * __expf(s_m[wi] - M);
    }
    __syncthreads();                       // all reads of s_acc done
    s_acc[g][d] = p4;

    // alpha writeout (CHUNK == blockDim)
    attn_w[(size_t)b * N_ + base + tid] = s_alpha[tid];
    __syncthreads();

    if (tid < D_) {
        float tot = 0.f;
#pragma unroll
        for (int gg = 0; gg < 8; gg++) tot += s_acc[gg][tid];
        g_pacc[(size_t)u * D_ + tid] = tot;
        if (tid == 0) { g_pm[u] = M; g_ps[u] = s_MS[1]; }
    }
}

// ---------------------------------------------------------------------------
// Kernel 3: per-b merge of SPLIT partials; writes attn_sum and normalizes
// the unnormalized alphas sitting in attn_w. grid=B, block=D.
// ---------------------------------------------------------------------------
__global__ void __launch_bounds__(D_) attn_merge(
    float* __restrict__ attn_w, float* __restrict__ attn_sum)
{
    const int b   = blockIdx.x;
    const int tid = threadIdx.x;
    const int u0  = b * 2, u1 = u0 + 1;

    const float m0 = g_pm[u0], m1 = g_pm[u1];
    const float M  = fmaxf(m0, m1);
    const float e0 = __expf(m0 - M);
    const float e1 = __expf(m1 - M);
    const float S  = g_ps[u0] * e0 + g_ps[u1] * e1;
    const float inv = 1.f / S;

    attn_sum[(size_t)b * D_ + tid] =
        (g_pacc[(size_t)u0 * D_ + tid] * e0 + g_pacc[(size_t)u1 * D_ + tid] * e1) * inv;

    float* wp = attn_w + (size_t)b * N_;
#pragma unroll
    for (int i = 0; i < N_ / D_; i++) {
        const int n = tid + i * D_;
        wp[n] = __expf(wp[n] - M) * inv;
    }
}

// ---------------------------------------------------------------------------
extern "C" void kernel_launch(void* const* d_in, const int* in_sizes, int n_in,
                              void* d_out, int out_size)
{
    const float* Q   = (const float*)d_in[0];   // (B,D)
    const float* K   = (const float*)d_in[1];   // (B,N,D)
    const float* V   = (const float*)d_in[2];   // (B,N,D)
    const float* adj = (const float*)d_in[3];   // (B,N)
    // d_in[4] = s_mask (unused)
    const float* W1  = (const float*)d_in[5];   // (D,D)
    const float* b1  = (const float*)d_in[6];   // (D,)
    const float* W2  = (const float*)d_in[7];   // (D,D)
    // d_in[8] = b2 (cancels in softmax)

    float* out_w   = (float*)d_out;                      // (B,1,N)
    float* out_sum = (float*)d_out + (size_t)B_ * N_;    // (B,D)

    float* qt;
    cudaGetSymbolAddress((void**)&qt, g_qt);

    qt_kernel<<<B_, D_>>>(Q, W1, b1, W2, qt);
    attn_main<<<UNITS, 1024>>>(K, V, adj, qt, out_w);
    attn_merge<<<B_, D_>>>(out_w, out_sum);
}